// round 14
// baseline (speedup 1.0000x reference)
#include <cuda_runtime.h>
#include <cuda_bf16.h>
#include <math.h>
#include <stdint.h>

#define SS 512
#define BB 64
#define II 1024
#define HH 1024
#define G4 4096   // 4*H
#define BHH (BB * HH)

#define NKB 8          // K-split factor for the step GEMM
#define NNB 16         // n-blocks (gate-coherent, 64 h-cols each)
#define BKC 128        // k-span per step block

// Scratch
__device__ float g_xw[(size_t)SS * BB * G4];       // 512 MB
__device__ float g_part[2][NKB][BB * G4];          // 16 MB (parity-buffered)
__device__ unsigned g_pdone[NNB];                  // partial stores done
__device__ unsigned g_cdone[NNB];                  // combines done (h ready / partial-WAR)
__device__ unsigned g_aload[NNB];                  // h consumptions done (h-WAR)

// bf16 hi/lo splits
__device__ __nv_bfloat16 g_xh[(size_t)SS * BB * II];   // 64 MB
__device__ __nv_bfloat16 g_xl[(size_t)SS * BB * II];
__device__ __nv_bfloat16 g_wh[(size_t)G4 * II];        // 8 MB
__device__ __nv_bfloat16 g_wl[(size_t)G4 * II];
__device__ __nv_bfloat16 g_uh[(size_t)G4 * HH];        // 8 MB
__device__ __nv_bfloat16 g_ul[(size_t)G4 * HH];
__device__ __nv_bfloat16 g_hh[2][BHH];                 // parity-buffered h
__device__ __nv_bfloat16 g_hl[2][BHH];

__device__ __forceinline__ float sigf(float x) {
    return 1.0f / (1.0f + __expf(-x));
}
__device__ __forceinline__ float tanhfast(float x) {
    return fmaf(2.0f, sigf(2.0f * x), -1.0f);
}

// ---------------- HMMA helpers (base-target ISA: sm_80+) ----------------
__device__ __forceinline__ uint32_t smem_u32(const void* p) {
    uint32_t a;
    asm("{ .reg .u64 t; cvta.to.shared.u64 t, %1; cvt.u32.u64 %0, t; }"
        : "=r"(a) : "l"(p));
    return a;
}
#define SW128(o) ((o) ^ (((o) >> 3) & 0x70))

__device__ __forceinline__ void hmma(float* c, const uint32_t* a, const uint32_t* b) {
    asm volatile(
        "mma.sync.aligned.m16n8k16.row.col.f32.bf16.bf16.f32 "
        "{%0,%1,%2,%3}, {%4,%5,%6,%7}, {%8,%9}, {%0,%1,%2,%3};"
        : "+f"(c[0]), "+f"(c[1]), "+f"(c[2]), "+f"(c[3])
        : "r"(a[0]), "r"(a[1]), "r"(a[2]), "r"(a[3]), "r"(b[0]), "r"(b[1]));
}
__device__ __forceinline__ void ldsm4(uint32_t* r, uint32_t addr) {
    asm volatile("ldmatrix.sync.aligned.m8n8.x4.shared.b16 {%0,%1,%2,%3}, [%4];"
        : "=r"(r[0]), "=r"(r[1]), "=r"(r[2]), "=r"(r[3]) : "r"(addr));
}
__device__ __forceinline__ void ldsm2(uint32_t* r, uint32_t addr) {
    asm volatile("ldmatrix.sync.aligned.m8n8.x2.shared.b16 {%0,%1}, [%2];"
        : "=r"(r[0]), "=r"(r[1]) : "r"(addr));
}
__device__ __forceinline__ void cpa16(uint32_t dst, const void* src) {
    asm volatile("cp.async.cg.shared.global [%0], [%1], 16;"
                 :: "r"(dst), "l"(src) : "memory");
}
__device__ __forceinline__ void cpa16_ca(uint32_t dst, const void* src) {
    asm volatile("cp.async.ca.shared.global [%0], [%1], 16;"
                 :: "r"(dst), "l"(src) : "memory");
}
#define CP_COMMIT() asm volatile("cp.async.commit_group;" ::: "memory")
#define CP_WAIT(n)  asm volatile("cp.async.wait_group %0;" :: "n"(n) : "memory")

__device__ __forceinline__ void spin_ge(unsigned* cnt, unsigned tgt) {
    while (atomicAdd(cnt, 0u) < tgt) __nanosleep(32);
}

// ---------------------------------------------------------------------------
// Split fp32 -> bf16 hi/lo (generic)
// ---------------------------------------------------------------------------
__device__ __forceinline__ void split4(float4 v, uint2& hi, uint2& lo) {
    __nv_bfloat16 h0 = __float2bfloat16(v.x), h1 = __float2bfloat16(v.y);
    __nv_bfloat16 h2 = __float2bfloat16(v.z), h3 = __float2bfloat16(v.w);
    __nv_bfloat16 l0 = __float2bfloat16(v.x - __bfloat162float(h0));
    __nv_bfloat16 l1 = __float2bfloat16(v.y - __bfloat162float(h1));
    __nv_bfloat16 l2 = __float2bfloat16(v.z - __bfloat162float(h2));
    __nv_bfloat16 l3 = __float2bfloat16(v.w - __bfloat162float(h3));
    __nv_bfloat162 ha(h0, h1), hb(h2, h3), la(l0, l1), lb(l2, l3);
    hi.x = *(uint32_t*)&ha; hi.y = *(uint32_t*)&hb;
    lo.x = *(uint32_t*)&la; lo.y = *(uint32_t*)&lb;
}

__global__ void cvt_split(const float* __restrict__ src,
                          __nv_bfloat16* __restrict__ dhi,
                          __nv_bfloat16* __restrict__ dlo) {
    const size_t i = (size_t)blockIdx.x * 256 + threadIdx.x;
    float4 v = *((const float4*)src + i);
    uint2 hi, lo;
    split4(v, hi, lo);
    ((uint2*)dhi)[i] = hi;
    ((uint2*)dlo)[i] = lo;
}

// ---------------------------------------------------------------------------
// Kernel A (HMMA): g_xw[m,g] = sum_i X[m,i]*W[g,i] + bias[g]  (R11 winner)
// ---------------------------------------------------------------------------
#define TCK 64
#define TERM 16384
#define STAGEB 65536
#define NSTG (II / TCK)

__global__ __launch_bounds__(256) void gemm_xw_hmma(const float* __restrict__ bias) {
    extern __shared__ __align__(1024) char dsm[];
    __shared__ float s_bias[128];

    const int tid = threadIdx.x;
    const int wid = tid >> 5;
    const int lid = tid & 31;
    const int wm = wid >> 2;
    const int wn = wid & 3;
    const int n0 = blockIdx.x << 7;
    const int m0 = blockIdx.y << 7;

    const uint32_t smbase = smem_u32(dsm);

    if (tid < 128) s_bias[tid] = bias[n0 + tid];

    const __nv_bfloat16* xh = g_xh + (size_t)m0 * II;
    const __nv_bfloat16* xl = g_xl + (size_t)m0 * II;
    const __nv_bfloat16* wh = g_wh + (size_t)n0 * II;
    const __nv_bfloat16* wl = g_wl + (size_t)n0 * II;

    uint32_t s_off[4];
    size_t g_off[4];
    #pragma unroll
    for (int j = 0; j < 4; j++) {
        const int idx = tid + (j << 8);
        const int r = idx >> 3;
        const int c = idx & 7;
        s_off[j] = SW128((uint32_t)(r * 128 + c * 16));
        g_off[j] = (size_t)r * II + c * 8;
    }

    uint32_t aRowRaw[4], bRowRaw[4];
    #pragma unroll
    for (int mi = 0; mi < 4; mi++)
        aRowRaw[mi] = (uint32_t)(((wm << 6) + (mi << 4) + (lid & 15)) * 128);
    #pragma unroll
    for (int ni = 0; ni < 4; ni++)
        bRowRaw[ni] = (uint32_t)(((wn << 5) + (ni << 3) + (lid & 7)) * 128);
    const uint32_t aChunk = (lid >> 4) << 4;
    const uint32_t bChunk = ((lid >> 3) & 1) << 4;

    float acc[4][4][4];
    #pragma unroll
    for (int mi = 0; mi < 4; mi++)
        #pragma unroll
        for (int ni = 0; ni < 4; ni++)
            #pragma unroll
            for (int q = 0; q < 4; q++) acc[mi][ni][q] = 0.0f;

    {
        const uint32_t sb = smbase;
        #pragma unroll
        for (int j = 0; j < 4; j++) {
            cpa16(sb + s_off[j],            xh + g_off[j]);
            cpa16(sb + TERM + s_off[j],     xl + g_off[j]);
            cpa16(sb + 2 * TERM + s_off[j], wh + g_off[j]);
            cpa16(sb + 3 * TERM + s_off[j], wl + g_off[j]);
        }
        CP_COMMIT();
    }

    for (int s = 0; s < NSTG; s++) {
        if (s + 1 < NSTG) {
            const uint32_t sb = smbase + ((s + 1) & 1) * STAGEB;
            const int k0 = (s + 1) * TCK;
            #pragma unroll
            for (int j = 0; j < 4; j++) {
                cpa16(sb + s_off[j],            xh + g_off[j] + k0);
                cpa16(sb + TERM + s_off[j],     xl + g_off[j] + k0);
                cpa16(sb + 2 * TERM + s_off[j], wh + g_off[j] + k0);
                cpa16(sb + 3 * TERM + s_off[j], wl + g_off[j] + k0);
            }
            CP_COMMIT();
            CP_WAIT(1);
        } else {
            CP_WAIT(0);
        }
        __syncthreads();

        const uint32_t sb = smbase + (s & 1) * STAGEB;
        #pragma unroll
        for (int kc = 0; kc < 4; kc++) {
            uint32_t ah[4][4], al[4][4], bh[4][2], bl[4][2];
            #pragma unroll
            for (int mi = 0; mi < 4; mi++) {
                const uint32_t ao = SW128(aRowRaw[mi] + (kc << 5) + aChunk);
                ldsm4(ah[mi], sb + ao);
                ldsm4(al[mi], sb + TERM + ao);
            }
            #pragma unroll
            for (int ni = 0; ni < 4; ni++) {
                const uint32_t bo = SW128(bRowRaw[ni] + (kc << 5) + bChunk);
                ldsm2(bh[ni], sb + 2 * TERM + bo);
                ldsm2(bl[ni], sb + 3 * TERM + bo);
            }
            #pragma unroll
            for (int mi = 0; mi < 4; mi++)
                #pragma unroll
                for (int ni = 0; ni < 4; ni++) {
                    hmma(acc[mi][ni], ah[mi], bh[ni]);
                    hmma(acc[mi][ni], ah[mi], bl[ni]);
                    hmma(acc[mi][ni], al[mi], bh[ni]);
                }
        }
        __syncthreads();
    }

    #pragma unroll
    for (int mi = 0; mi < 4; mi++) {
        const int mA = m0 + (wm << 6) + (mi << 4) + (lid >> 2);
        #pragma unroll
        for (int ni = 0; ni < 4; ni++) {
            const int colB = (wn << 5) + (ni << 3) + ((lid & 3) << 1);
            const float b0 = s_bias[colB], b1 = s_bias[colB + 1];
            float2 o0 = {acc[mi][ni][0] + b0, acc[mi][ni][1] + b1};
            float2 o1 = {acc[mi][ni][2] + b0, acc[mi][ni][3] + b1};
            *(float2*)(g_xw + (size_t)mA * G4 + n0 + colB)       = o0;
            *(float2*)(g_xw + (size_t)(mA + 8) * G4 + n0 + colB) = o1;
        }
    }
}

// ---------------------------------------------------------------------------
// Kernel B: PERSISTENT LSTM, dataflow-synchronized (no global barriers).
//   128 blocks (nb=bid>>3, kb=bid&7), 256 threads, single wave.
//   U slice SMEM-resident; h and partials parity-buffered in gmem;
//   c lives in registers (each thread owns fixed coords for all steps).
//   Counters (per nb group, monotonic):
//     g_cdone: combine done  (8/step)  -> h ready + partial-WAR release
//     g_pdone: partials done (8/step)  -> combine RAW
//     g_aload: A-loads done (16/step)  -> h-WAR release
//   Block (nb,kb) step t:
//     wait cdone[2kb],cdone[2kb+1] >= 8t  (h inputs ready)
//          cdone[nb] >= 8(t-1)            (own partial buffer drained)
//     A load (parity t&1) -> signal aload[2kb], aload[2kb+1]
//     HMMA -> store partials (parity t&1) -> signal pdone[nb]
//     wait pdone[nb] >= 8(t+1), aload[nb] >= 16t (h buffer t+1 drained)
//     combine -> h fp32 out + bf16 parity (t+1)&1 -> signal cdone[nb]
// ---------------------------------------------------------------------------
#define A_HI 0
#define A_LO 16384
#define B_HI 32768
#define B_LO 98304
#define SMEMB 163840
#define A_ATOM 8192     // 64 rows * 128B
#define B_ATOM 32768    // 256 rows * 128B

__global__ __launch_bounds__(256) void lstm_persist_tc(const float* __restrict__ c0,
                                                       float* __restrict__ out) {
    extern __shared__ __align__(1024) char dsm[];

    const int bid = blockIdx.x;
    const int nb = bid >> 3;              // 0..15
    const int kb = bid & 7;               // 0..7
    const int ha = kb << 1;               // h source group A
    const int hb = ha + 1;                // h source group B
    const int tid = threadIdx.x;
    const int wid = tid >> 5;
    const int lid = tid & 31;

    const uint32_t smbase = smem_u32(dsm);

    // ---- loader precompute (A offsets within a parity buffer) ----
    uint32_t aso[4];
    size_t   ago[4];
    #pragma unroll
    for (int j = 0; j < 4; j++) {
        const int idx = tid + (j << 8);
        const int r = idx >> 4, c = idx & 15;
        aso[j] = (uint32_t)((c >> 3) * A_ATOM) +
                 SW128((uint32_t)(r * 128 + (c & 7) * 16));
        ago[j] = (size_t)r * HH + kb * BKC + c * 8;
    }

    // ---- B (U slice) load: ONCE, stays resident ----
    #pragma unroll
    for (int j = 0; j < 16; j++) {
        const int idx = tid + (j << 8);
        const int r = idx >> 4, c = idx & 15;
        const int G = ((r >> 6) << 10) + (nb << 6) + (r & 63);
        const uint32_t bso = (uint32_t)((c >> 3) * B_ATOM) +
                             SW128((uint32_t)(r * 128 + (c & 7) * 16));
        const size_t bgo = (size_t)G * HH + kb * BKC + c * 8;
        cpa16_ca(smbase + B_HI + bso, g_uh + bgo);
        cpa16_ca(smbase + B_LO + bso, g_ul + bgo);
    }
    CP_COMMIT();

    // ldmatrix row bases
    uint32_t aRowRaw[4], bRowRaw[4];
    #pragma unroll
    for (int mi = 0; mi < 4; mi++)
        aRowRaw[mi] = (uint32_t)(((mi << 4) + (lid & 15)) * 128);
    #pragma unroll
    for (int ni = 0; ni < 4; ni++)
        bRowRaw[ni] = (uint32_t)(((wid << 5) + (ni << 3) + (lid & 7)) * 128);
    const uint32_t aChunk = (lid >> 4) << 4;
    const uint32_t bChunk = ((lid >> 3) & 1) << 4;

    // combine coords (fixed per thread for all steps)
    const int cb  = tid >> 2;
    const int hcol = (nb << 6) + (kb << 3) + ((tid & 3) << 1);
    const int idx = cb * HH + hcol;

    // cell state in registers for the whole sequence
    float2 creg = *(const float2*)(c0 + idx);

    CP_WAIT(0);
    __syncthreads();

    for (int t = 0; t < SS; t++) {
        const int ph = t & 1;

        // ---------------- input-ready + partial-WAR wait ----------------
        if (tid == 0) {
            if (t) {
                const unsigned tgt = 8u * (unsigned)t;
                spin_ge(&g_cdone[ha], tgt);
                spin_ge(&g_cdone[hb], tgt);
            }
            if (t >= 2) spin_ge(&g_cdone[nb], 8u * (unsigned)(t - 1));
        }
        __syncthreads();

        // ---------------- load A tile (h hi/lo, parity ph) ----------------
        {
            const __nv_bfloat16* hhp = g_hh[ph];
            const __nv_bfloat16* hlp = g_hl[ph];
            #pragma unroll
            for (int j = 0; j < 4; j++) {
                cpa16(smbase + A_HI + aso[j], hhp + ago[j]);
                cpa16(smbase + A_LO + aso[j], hlp + ago[j]);
            }
        }
        CP_COMMIT();
        CP_WAIT(0);
        __syncthreads();
        if (tid == 0) {
            atomicAdd(&g_aload[ha], 1u);
            atomicAdd(&g_aload[hb], 1u);
        }

        // ---------------- HMMA: 64m x 256n x 128k, 3 terms ----------------
        float acc[4][4][4];
        #pragma unroll
        for (int mi = 0; mi < 4; mi++)
            #pragma unroll
            for (int ni = 0; ni < 4; ni++)
                #pragma unroll
                for (int q = 0; q < 4; q++) acc[mi][ni][q] = 0.0f;

        #pragma unroll
        for (int kk = 0; kk < 8; kk++) {
            const uint32_t aAt = (uint32_t)((kk >> 2) * A_ATOM);
            const uint32_t bAt = (uint32_t)((kk >> 2) * B_ATOM);
            const uint32_t kco = (uint32_t)((kk & 3) << 5);

            uint32_t ah4[4][4], al4[4][4], bh4[4][2], bl4[4][2];
            #pragma unroll
            for (int mi = 0; mi < 4; mi++) {
                const uint32_t ao = aAt + SW128(aRowRaw[mi] + kco + aChunk);
                ldsm4(ah4[mi], smbase + A_HI + ao);
                ldsm4(al4[mi], smbase + A_LO + ao);
            }
            #pragma unroll
            for (int ni = 0; ni < 4; ni++) {
                const uint32_t bo = bAt + SW128(bRowRaw[ni] + kco + bChunk);
                ldsm2(bh4[ni], smbase + B_HI + bo);
                ldsm2(bl4[ni], smbase + B_LO + bo);
            }
            #pragma unroll
            for (int mi = 0; mi < 4; mi++)
                #pragma unroll
                for (int ni = 0; ni < 4; ni++) {
                    hmma(acc[mi][ni], ah4[mi], bh4[ni]);
                    hmma(acc[mi][ni], ah4[mi], bl4[ni]);
                    hmma(acc[mi][ni], al4[mi], bh4[ni]);
                }
        }

        // ---------------- store partials (parity ph) ----------------
        {
            float* pout = g_part[ph][kb];
            #pragma unroll
            for (int mi = 0; mi < 4; mi++) {
                const int m = (mi << 4) + (lid >> 2);
                #pragma unroll
                for (int ni = 0; ni < 4; ni++) {
                    const int c = (wid << 5) + (ni << 3) + ((lid & 3) << 1);
                    const int G = ((c >> 6) << 10) + (nb << 6) + (c & 63);
                    float2 o0 = {acc[mi][ni][0], acc[mi][ni][1]};
                    float2 o1 = {acc[mi][ni][2], acc[mi][ni][3]};
                    *(float2*)(pout + (size_t)m * G4 + G)       = o0;
                    *(float2*)(pout + (size_t)(m + 8) * G4 + G) = o1;
                }
            }
        }
        __threadfence();

        // Prefetch xW gate values while waiting.
        float2 gate[4];
        #pragma unroll
        for (int g = 0; g < 4; g++) {
            const size_t off = (size_t)cb * G4 + (g << 10) + hcol;
            gate[g] = *(const float2*)(g_xw + (size_t)t * BB * G4 + off);
        }

        __syncthreads();
        if (tid == 0) {
            atomicAdd(&g_pdone[nb], 1u);
            spin_ge(&g_pdone[nb], 8u * (unsigned)(t + 1));
            if (t) spin_ge(&g_aload[nb], 16u * (unsigned)t);
        }
        __syncthreads();

        // ---------------- combine + elementwise ----------------
        {
            #pragma unroll
            for (int g = 0; g < 4; g++) {
                const size_t off = (size_t)cb * G4 + (g << 10) + hcol;
                #pragma unroll
                for (int p = 0; p < NKB; p++) {
                    const float2 pv = __ldcg((const float2*)(g_part[ph][p] + off));
                    gate[g].x += pv.x; gate[g].y += pv.y;
                }
            }

            float2 cn, hv;
            {
                const float iv = sigf(gate[0].x), fv = sigf(gate[1].x);
                const float gv = tanhfast(gate[2].x), ov = sigf(gate[3].x);
                cn.x = fv * creg.x + iv * gv;  hv.x = ov * tanhfast(cn.x);
            }
            {
                const float iv = sigf(gate[0].y), fv = sigf(gate[1].y);
                const float gv = tanhfast(gate[2].y), ov = sigf(gate[3].y);
                cn.y = fv * creg.y + iv * gv;  hv.y = ov * tanhfast(cn.y);
            }
            creg = cn;
            *(float2*)(out + (size_t)t * BHH + idx) = hv;

            __nv_bfloat16 h0b = __float2bfloat16(hv.x);
            __nv_bfloat16 h1b = __float2bfloat16(hv.y);
            __nv_bfloat16 l0b = __float2bfloat16(hv.x - __bfloat162float(h0b));
            __nv_bfloat16 l1b = __float2bfloat16(hv.y - __bfloat162float(h1b));
            __nv_bfloat162 hp(h0b, h1b), lp(l0b, l1b);
            *(__nv_bfloat162*)(g_hh[ph ^ 1] + idx) = hp;
            *(__nv_bfloat162*)(g_hl[ph ^ 1] + idx) = lp;

            if (t == SS - 1) {
                const size_t base = (size_t)SS * BHH;
                *(float2*)(out + base + idx) = hv;          // h_t
                *(float2*)(out + base + BHH + idx) = cn;    // c_t
            }
        }

        __threadfence();
        __syncthreads();
        if (tid == 0) atomicAdd(&g_cdone[nb], 1u);
    }
}

// ---------------------------------------------------------------------------
// Helpers
// ---------------------------------------------------------------------------
__global__ void seed_state(const float* __restrict__ h0) {
    const int i = blockIdx.x * 256 + threadIdx.x;
    const float h = h0[i];
    const __nv_bfloat16 hh = __float2bfloat16(h);
    g_hh[0][i] = hh;
    g_hl[0][i] = __float2bfloat16(h - __bfloat162float(hh));
    if (blockIdx.x == 0 && threadIdx.x < NNB) {
        g_pdone[threadIdx.x] = 0u;
        g_cdone[threadIdx.x] = 0u;
        g_aload[threadIdx.x] = 0u;
    }
}

// ---------------------------------------------------------------------------
extern "C" void kernel_launch(void* const* d_in, const int* in_sizes, int n_in,
                              void* d_out, int out_size) {
    (void)in_sizes; (void)n_in; (void)out_size;
    const float* x  = (const float*)d_in[0];
    const float* h0 = (const float*)d_in[1];
    const float* c0 = (const float*)d_in[2];
    const float* Ww = (const float*)d_in[3];
    const float* Wb = (const float*)d_in[4];
    const float* Uw = (const float*)d_in[5];
    float* out = (float*)d_out;

    cudaFuncSetAttribute(gemm_xw_hmma,
                         cudaFuncAttributeMaxDynamicSharedMemorySize,
                         2 * STAGEB);
    cudaFuncSetAttribute(lstm_persist_tc,
                         cudaFuncAttributeMaxDynamicSharedMemorySize,
                         SMEMB);

    seed_state<<<BHH / 256, 256>>>(h0);

    __nv_bfloat16 *xh, *xl, *wh, *wl, *uh, *ul;
    cudaGetSymbolAddress((void**)&xh, g_xh);
    cudaGetSymbolAddress((void**)&xl, g_xl);
    cudaGetSymbolAddress((void**)&wh, g_wh);
    cudaGetSymbolAddress((void**)&wl, g_wl);
    cudaGetSymbolAddress((void**)&uh, g_uh);
    cudaGetSymbolAddress((void**)&ul, g_ul);

    cvt_split<<<(SS * BB * II / 4) / 256, 256>>>(x, xh, xl);
    cvt_split<<<(G4 * II / 4) / 256, 256>>>(Ww, wh, wl);
    cvt_split<<<(G4 * HH / 4) / 256, 256>>>(Uw, uh, ul);

    gemm_xw_hmma<<<dim3(G4 / 128, (SS * BB) / 128), 256, 2 * STAGEB>>>(Wb);

    lstm_persist_tc<<<NNB * NKB, 256, SMEMB>>>(c0, out);
}

// round 15
// speedup vs baseline: 1.1207x; 1.1207x over previous
#include <cuda_runtime.h>
#include <cuda_bf16.h>
#include <math.h>
#include <stdint.h>

#define SS 512
#define BB 64
#define II 1024
#define HH 1024
#define G4 4096   // 4*H
#define BHH (BB * HH)

// Scratch
__device__ float g_xw[(size_t)SS * BB * G4];       // 512 MB
__device__ unsigned g_stepcnt;

// bf16 hi/lo splits
__device__ __nv_bfloat16 g_xh[(size_t)SS * BB * II];   // 64 MB
__device__ __nv_bfloat16 g_xl[(size_t)SS * BB * II];
__device__ __nv_bfloat16 g_wh[(size_t)G4 * II];        // 8 MB
__device__ __nv_bfloat16 g_wl[(size_t)G4 * II];
__device__ __nv_bfloat16 g_uh[(size_t)G4 * HH];        // 8 MB
__device__ __nv_bfloat16 g_ul[(size_t)G4 * HH];
__device__ __nv_bfloat16 g_hh[2][BHH];                 // parity-buffered h
__device__ __nv_bfloat16 g_hl[2][BHH];

__device__ __forceinline__ float sigf(float x) {
    return 1.0f / (1.0f + __expf(-x));
}
__device__ __forceinline__ float tanhfast(float x) {
    return fmaf(2.0f, sigf(2.0f * x), -1.0f);
}

// ---------------- HMMA helpers (base-target ISA: sm_80+) ----------------
__device__ __forceinline__ uint32_t smem_u32(const void* p) {
    uint32_t a;
    asm("{ .reg .u64 t; cvta.to.shared.u64 t, %1; cvt.u32.u64 %0, t; }"
        : "=r"(a) : "l"(p));
    return a;
}
#define SW128(o) ((o) ^ (((o) >> 3) & 0x70))

__device__ __forceinline__ void hmma(float* c, const uint32_t* a, const uint32_t* b) {
    asm volatile(
        "mma.sync.aligned.m16n8k16.row.col.f32.bf16.bf16.f32 "
        "{%0,%1,%2,%3}, {%4,%5,%6,%7}, {%8,%9}, {%0,%1,%2,%3};"
        : "+f"(c[0]), "+f"(c[1]), "+f"(c[2]), "+f"(c[3])
        : "r"(a[0]), "r"(a[1]), "r"(a[2]), "r"(a[3]), "r"(b[0]), "r"(b[1]));
}
__device__ __forceinline__ void ldsm4(uint32_t* r, uint32_t addr) {
    asm volatile("ldmatrix.sync.aligned.m8n8.x4.shared.b16 {%0,%1,%2,%3}, [%4];"
        : "=r"(r[0]), "=r"(r[1]), "=r"(r[2]), "=r"(r[3]) : "r"(addr));
}
__device__ __forceinline__ void ldsm2(uint32_t* r, uint32_t addr) {
    asm volatile("ldmatrix.sync.aligned.m8n8.x2.shared.b16 {%0,%1}, [%2];"
        : "=r"(r[0]), "=r"(r[1]) : "r"(addr));
}
__device__ __forceinline__ void cpa16(uint32_t dst, const void* src) {
    asm volatile("cp.async.cg.shared.global [%0], [%1], 16;"
                 :: "r"(dst), "l"(src) : "memory");
}
__device__ __forceinline__ void cpa16_ca(uint32_t dst, const void* src) {
    asm volatile("cp.async.ca.shared.global [%0], [%1], 16;"
                 :: "r"(dst), "l"(src) : "memory");
}
#define CP_COMMIT() asm volatile("cp.async.commit_group;" ::: "memory")
#define CP_WAIT(n)  asm volatile("cp.async.wait_group %0;" :: "n"(n) : "memory")

// ---------------------------------------------------------------------------
// Split fp32 -> bf16 hi/lo (generic)
// ---------------------------------------------------------------------------
__device__ __forceinline__ void split4(float4 v, uint2& hi, uint2& lo) {
    __nv_bfloat16 h0 = __float2bfloat16(v.x), h1 = __float2bfloat16(v.y);
    __nv_bfloat16 h2 = __float2bfloat16(v.z), h3 = __float2bfloat16(v.w);
    __nv_bfloat16 l0 = __float2bfloat16(v.x - __bfloat162float(h0));
    __nv_bfloat16 l1 = __float2bfloat16(v.y - __bfloat162float(h1));
    __nv_bfloat16 l2 = __float2bfloat16(v.z - __bfloat162float(h2));
    __nv_bfloat16 l3 = __float2bfloat16(v.w - __bfloat162float(h3));
    __nv_bfloat162 ha(h0, h1), hb(h2, h3), la(l0, l1), lb(l2, l3);
    hi.x = *(uint32_t*)&ha; hi.y = *(uint32_t*)&hb;
    lo.x = *(uint32_t*)&la; lo.y = *(uint32_t*)&lb;
}

__global__ void cvt_split(const float* __restrict__ src,
                          __nv_bfloat16* __restrict__ dhi,
                          __nv_bfloat16* __restrict__ dlo) {
    const size_t i = (size_t)blockIdx.x * 256 + threadIdx.x;
    float4 v = *((const float4*)src + i);
    uint2 hi, lo;
    split4(v, hi, lo);
    ((uint2*)dhi)[i] = hi;
    ((uint2*)dlo)[i] = lo;
}

// ---------------------------------------------------------------------------
// Kernel A (HMMA): g_xw[m,g] = sum_i X[m,i]*W[g,i] + bias[g]  (R11 winner)
// ---------------------------------------------------------------------------
#define TCK 64
#define TERM 16384
#define STAGEB 65536
#define NSTG (II / TCK)

__global__ __launch_bounds__(256) void gemm_xw_hmma(const float* __restrict__ bias) {
    extern __shared__ __align__(1024) char dsm[];
    __shared__ float s_bias[128];

    const int tid = threadIdx.x;
    const int wid = tid >> 5;
    const int lid = tid & 31;
    const int wm = wid >> 2;
    const int wn = wid & 3;
    const int n0 = blockIdx.x << 7;
    const int m0 = blockIdx.y << 7;

    const uint32_t smbase = smem_u32(dsm);

    if (tid < 128) s_bias[tid] = bias[n0 + tid];

    const __nv_bfloat16* xh = g_xh + (size_t)m0 * II;
    const __nv_bfloat16* xl = g_xl + (size_t)m0 * II;
    const __nv_bfloat16* wh = g_wh + (size_t)n0 * II;
    const __nv_bfloat16* wl = g_wl + (size_t)n0 * II;

    uint32_t s_off[4];
    size_t g_off[4];
    #pragma unroll
    for (int j = 0; j < 4; j++) {
        const int idx = tid + (j << 8);
        const int r = idx >> 3;
        const int c = idx & 7;
        s_off[j] = SW128((uint32_t)(r * 128 + c * 16));
        g_off[j] = (size_t)r * II + c * 8;
    }

    uint32_t aRowRaw[4], bRowRaw[4];
    #pragma unroll
    for (int mi = 0; mi < 4; mi++)
        aRowRaw[mi] = (uint32_t)(((wm << 6) + (mi << 4) + (lid & 15)) * 128);
    #pragma unroll
    for (int ni = 0; ni < 4; ni++)
        bRowRaw[ni] = (uint32_t)(((wn << 5) + (ni << 3) + (lid & 7)) * 128);
    const uint32_t aChunk = (lid >> 4) << 4;
    const uint32_t bChunk = ((lid >> 3) & 1) << 4;

    float acc[4][4][4];
    #pragma unroll
    for (int mi = 0; mi < 4; mi++)
        #pragma unroll
        for (int ni = 0; ni < 4; ni++)
            #pragma unroll
            for (int q = 0; q < 4; q++) acc[mi][ni][q] = 0.0f;

    {
        const uint32_t sb = smbase;
        #pragma unroll
        for (int j = 0; j < 4; j++) {
            cpa16(sb + s_off[j],            xh + g_off[j]);
            cpa16(sb + TERM + s_off[j],     xl + g_off[j]);
            cpa16(sb + 2 * TERM + s_off[j], wh + g_off[j]);
            cpa16(sb + 3 * TERM + s_off[j], wl + g_off[j]);
        }
        CP_COMMIT();
    }

    for (int s = 0; s < NSTG; s++) {
        if (s + 1 < NSTG) {
            const uint32_t sb = smbase + ((s + 1) & 1) * STAGEB;
            const int k0 = (s + 1) * TCK;
            #pragma unroll
            for (int j = 0; j < 4; j++) {
                cpa16(sb + s_off[j],            xh + g_off[j] + k0);
                cpa16(sb + TERM + s_off[j],     xl + g_off[j] + k0);
                cpa16(sb + 2 * TERM + s_off[j], wh + g_off[j] + k0);
                cpa16(sb + 3 * TERM + s_off[j], wl + g_off[j] + k0);
            }
            CP_COMMIT();
            CP_WAIT(1);
        } else {
            CP_WAIT(0);
        }
        __syncthreads();

        const uint32_t sb = smbase + (s & 1) * STAGEB;
        #pragma unroll
        for (int kc = 0; kc < 4; kc++) {
            uint32_t ah[4][4], al[4][4], bh[4][2], bl[4][2];
            #pragma unroll
            for (int mi = 0; mi < 4; mi++) {
                const uint32_t ao = SW128(aRowRaw[mi] + (kc << 5) + aChunk);
                ldsm4(ah[mi], sb + ao);
                ldsm4(al[mi], sb + TERM + ao);
            }
            #pragma unroll
            for (int ni = 0; ni < 4; ni++) {
                const uint32_t bo = SW128(bRowRaw[ni] + (kc << 5) + bChunk);
                ldsm2(bh[ni], sb + 2 * TERM + bo);
                ldsm2(bl[ni], sb + 3 * TERM + bo);
            }
            #pragma unroll
            for (int mi = 0; mi < 4; mi++)
                #pragma unroll
                for (int ni = 0; ni < 4; ni++) {
                    hmma(acc[mi][ni], ah[mi], bh[ni]);
                    hmma(acc[mi][ni], ah[mi], bl[ni]);
                    hmma(acc[mi][ni], al[mi], bh[ni]);
                }
        }
        __syncthreads();
    }

    #pragma unroll
    for (int mi = 0; mi < 4; mi++) {
        const int mA = m0 + (wm << 6) + (mi << 4) + (lid >> 2);
        #pragma unroll
        for (int ni = 0; ni < 4; ni++) {
            const int colB = (wn << 5) + (ni << 3) + ((lid & 3) << 1);
            const float b0 = s_bias[colB], b1 = s_bias[colB + 1];
            float2 o0 = {acc[mi][ni][0] + b0, acc[mi][ni][1] + b1};
            float2 o1 = {acc[mi][ni][2] + b0, acc[mi][ni][3] + b1};
            *(float2*)(g_xw + (size_t)mA * G4 + n0 + colB)       = o0;
            *(float2*)(g_xw + (size_t)(mA + 8) * G4 + n0 + colB) = o1;
        }
    }
}

// ---------------------------------------------------------------------------
// Kernel B: PERSISTENT LSTM v2 — full-K per block, ONE sync per step.
//   128 blocks, block bid owns h-cols [bid*8, bid*8+8) (= 32 gate cols,
//   gate-coherent). B = U slice [32 rows x 1024 k] hi/lo SMEM-resident
//   (128 KB). A = full h [64 x 1024] hi/lo streamed per step through a
//   3-deep ring of 32 KB chunks (k=128 each), cp.async.cg.
//   Warp (wm=wid>>1, wn=wid&1) owns a 16m x 16n tile over ALL k -> gates
//   complete in-block; local combine; c in registers; h parity-buffered.
//   Single grid counter per step (poll via volatile load).
// ---------------------------------------------------------------------------
#define ABUFB 32768            // per ring slot: HI 16KB + LO 16KB
#define A_LO_OFF 16384
#define SM_B_HI 98304          // 3*ABUFB
#define SM_B_LO 163840
#define SMEMB2 229376
#define A_ATOM2 8192           // 64 rows * 128B
#define B_ATOM2 4096           // 32 rows * 128B

__global__ __launch_bounds__(256) void lstm_persist_v2(const float* __restrict__ c0,
                                                       float* __restrict__ out) {
    extern __shared__ __align__(1024) char dsm[];

    const int bid = blockIdx.x;           // 0..127
    const int hc0 = bid << 3;             // h-col base
    const int tid = threadIdx.x;
    const int wid = tid >> 5;
    const int lid = tid & 31;
    const int wm = wid >> 1;              // 0..3 m-tile (16 rows)
    const int wn = wid & 1;               // 0..1 n-half (16 cols)

    const uint32_t smbase = smem_u32(dsm);

    // ---- B (U slice, 32 rows x 1024 k, hi+lo) load ONCE ----
    #pragma unroll
    for (int j = 0; j < 16; j++) {
        const int idx = tid + (j << 8);
        const int a = idx >> 8;               // k-atom 0..15
        const int w = idx & 255;
        const int r = w >> 3;                 // n row 0..31 (= g*8 + jcol)
        const int cc = w & 7;
        const int Grow = ((r >> 3) << 10) + hc0 + (r & 7);
        const uint32_t so = (uint32_t)(a * B_ATOM2) +
                            SW128((uint32_t)(r * 128 + cc * 16));
        const size_t go = (size_t)Grow * HH + a * 64 + cc * 8;
        cpa16_ca(smbase + SM_B_HI + so, g_uh + go);
        cpa16_ca(smbase + SM_B_LO + so, g_ul + go);
    }
    CP_COMMIT();

    // ---- A per-chunk loader precompute (chunk = 128 k = 2 atoms) ----
    uint32_t aso[4];
    int agoR[4], agoK[4];
    #pragma unroll
    for (int j = 0; j < 4; j++) {
        const int idx = tid + (j << 8);       // 0..1023 per term
        const int a2 = idx >> 9;              // atom in chunk 0..1
        const int w = idx & 511;
        const int r = w >> 3;                 // batch row 0..63
        const int cc = w & 7;
        aso[j] = (uint32_t)(a2 * A_ATOM2) +
                 SW128((uint32_t)(r * 128 + cc * 16));
        agoR[j] = r;
        agoK[j] = a2 * 64 + cc * 8;
    }

    // ---- ldmatrix bases ----
    const uint32_t aRow = (uint32_t)(((wm << 4) + (lid & 15)) * 128);
    const uint32_t aChunk = (lid >> 4) << 4;
    uint32_t bRowRaw[2];
    #pragma unroll
    for (int ni = 0; ni < 2; ni++)
        bRowRaw[ni] = (uint32_t)(((wn << 4) + (ni << 3) + (lid & 7)) * 128);
    const uint32_t bChunk = ((lid >> 3) & 1) << 4;

    // ---- combine coords (fixed per thread) ----
    const int cb = tid >> 2;                  // batch 0..63
    const int jj = (tid & 3) << 1;            // 0,2,4,6
    const int idxo = cb * HH + hc0 + jj;

    float2 creg = *(const float2*)(c0 + idxo);

    CP_WAIT(0);
    __syncthreads();

    volatile unsigned* sc = &g_stepcnt;

    for (int t = 0; t < SS; t++) {
        const int ph = t & 1;

        // xW prefetch — independent of the barrier, issue early.
        float2 gate[4];
        #pragma unroll
        for (int g = 0; g < 4; g++)
            gate[g] = *(const float2*)(g_xw + ((size_t)t * BB + cb) * G4 +
                                       (g << 10) + hc0 + jj);

        // ---- single grid sync: h(t) ready ----
        if (t && tid == 0) {
            const unsigned tgt = 128u * (unsigned)t;
            while (*sc < tgt) __nanosleep(32);
        }
        __syncthreads();

        const __nv_bfloat16* hhp = g_hh[ph];
        const __nv_bfloat16* hlp = g_hl[ph];

        // prologue: chunks 0 and 1
        #pragma unroll
        for (int p = 0; p < 2; p++) {
            const uint32_t ab = smbase + p * ABUFB;
            #pragma unroll
            for (int j = 0; j < 4; j++) {
                const size_t go = (size_t)agoR[j] * HH + p * 128 + agoK[j];
                cpa16(ab + aso[j], hhp + go);
                cpa16(ab + A_LO_OFF + aso[j], hlp + go);
            }
            CP_COMMIT();
        }

        float acc[2][4];
        #pragma unroll
        for (int ni = 0; ni < 2; ni++)
            #pragma unroll
            for (int q = 0; q < 4; q++) acc[ni][q] = 0.0f;

        #pragma unroll
        for (int ch = 0; ch < 8; ch++) {
            if (ch < 7) { CP_WAIT(1); } else { CP_WAIT(0); }
            __syncthreads();

            if (ch + 2 < 8) {
                const uint32_t ab = smbase + ((ch + 2) % 3) * ABUFB;
                #pragma unroll
                for (int j = 0; j < 4; j++) {
                    const size_t go = (size_t)agoR[j] * HH + (ch + 2) * 128 + agoK[j];
                    cpa16(ab + aso[j], hhp + go);
                    cpa16(ab + A_LO_OFF + aso[j], hlp + go);
                }
                CP_COMMIT();
            }

            const uint32_t ab = smbase + (ch % 3) * ABUFB;
            #pragma unroll
            for (int kk = 0; kk < 8; kk++) {
                const uint32_t aAt = (uint32_t)((kk >> 2) * A_ATOM2);
                const uint32_t kco = (uint32_t)((kk & 3) << 5);
                const uint32_t bAt = (uint32_t)((ch * 2 + (kk >> 2)) * B_ATOM2);

                uint32_t ah4[4], al4[4], bh2[2][2], bl2[2][2];
                const uint32_t ao = aAt + SW128(aRow + kco + aChunk);
                ldsm4(ah4, ab + ao);
                ldsm4(al4, ab + A_LO_OFF + ao);
                #pragma unroll
                for (int ni = 0; ni < 2; ni++) {
                    const uint32_t bo = bAt + SW128(bRowRaw[ni] + kco + bChunk);
                    ldsm2(bh2[ni], smbase + SM_B_HI + bo);
                    ldsm2(bl2[ni], smbase + SM_B_LO + bo);
                }
                #pragma unroll
                for (int ni = 0; ni < 2; ni++) {
                    hmma(acc[ni], ah4, bh2[ni]);
                    hmma(acc[ni], ah4, bl2[ni]);
                    hmma(acc[ni], al4, bh2[ni]);
                }
            }
        }

        // ---- gates to SMEM (reuse ring slot 0; drained: all warps passed
        //      the ch=7 wait+sync, and slot 0 was last touched at ch=6) ----
        {
            float* gs = (float*)dsm;   // [64][34] fp32 = 8704 B < 16 KB
            #pragma unroll
            for (int ni = 0; ni < 2; ni++) {
                const int col = (wn << 4) + (ni << 3) + ((lid & 3) << 1);
                const int row = (wm << 4) + (lid >> 2);
                *(float2*)&gs[row * 34 + col] = make_float2(acc[ni][0], acc[ni][1]);
                *(float2*)&gs[(row + 8) * 34 + col] = make_float2(acc[ni][2], acc[ni][3]);
            }
        }
        __syncthreads();

        // ---- combine + elementwise ----
        {
            const float* gs = (const float*)dsm;
            #pragma unroll
            for (int g = 0; g < 4; g++) {
                gate[g].x += gs[cb * 34 + (g << 3) + jj];
                gate[g].y += gs[cb * 34 + (g << 3) + jj + 1];
            }

            float2 cn, hv;
            {
                const float iv = sigf(gate[0].x), fv = sigf(gate[1].x);
                const float gv = tanhfast(gate[2].x), ov = sigf(gate[3].x);
                cn.x = fv * creg.x + iv * gv;  hv.x = ov * tanhfast(cn.x);
            }
            {
                const float iv = sigf(gate[0].y), fv = sigf(gate[1].y);
                const float gv = tanhfast(gate[2].y), ov = sigf(gate[3].y);
                cn.y = fv * creg.y + iv * gv;  hv.y = ov * tanhfast(cn.y);
            }
            creg = cn;
            *(float2*)(out + (size_t)t * BHH + idxo) = hv;

            __nv_bfloat16 h0b = __float2bfloat16(hv.x);
            __nv_bfloat16 h1b = __float2bfloat16(hv.y);
            __nv_bfloat16 l0b = __float2bfloat16(hv.x - __bfloat162float(h0b));
            __nv_bfloat16 l1b = __float2bfloat16(hv.y - __bfloat162float(h1b));
            __nv_bfloat162 hp(h0b, h1b), lp(l0b, l1b);
            *(__nv_bfloat162*)(g_hh[ph ^ 1] + idxo) = hp;
            *(__nv_bfloat162*)(g_hl[ph ^ 1] + idxo) = lp;

            if (t == SS - 1) {
                const size_t base = (size_t)SS * BHH;
                *(float2*)(out + base + idxo) = hv;          // h_t
                *(float2*)(out + base + BHH + idxo) = cn;    // c_t
            }
        }

        // ---- publish ----
        __threadfence();
        __syncthreads();
        if (tid == 0) atomicAdd(&g_stepcnt, 1u);
        __syncthreads();   // keep smem gates stable until all read (done above)
    }
}

// ---------------------------------------------------------------------------
// Helpers
// ---------------------------------------------------------------------------
__global__ void seed_state(const float* __restrict__ h0) {
    const int i = blockIdx.x * 256 + threadIdx.x;
    const float h = h0[i];
    const __nv_bfloat16 hh = __float2bfloat16(h);
    g_hh[0][i] = hh;
    g_hl[0][i] = __float2bfloat16(h - __bfloat162float(hh));
    if (blockIdx.x == 0 && threadIdx.x == 0) g_stepcnt = 0u;
}

// ---------------------------------------------------------------------------
extern "C" void kernel_launch(void* const* d_in, const int* in_sizes, int n_in,
                              void* d_out, int out_size) {
    (void)in_sizes; (void)n_in; (void)out_size;
    const float* x  = (const float*)d_in[0];
    const float* h0 = (const float*)d_in[1];
    const float* c0 = (const float*)d_in[2];
    const float* Ww = (const float*)d_in[3];
    const float* Wb = (const float*)d_in[4];
    const float* Uw = (const float*)d_in[5];
    float* out = (float*)d_out;

    cudaFuncSetAttribute(gemm_xw_hmma,
                         cudaFuncAttributeMaxDynamicSharedMemorySize,
                         2 * STAGEB);
    cudaFuncSetAttribute(lstm_persist_v2,
                         cudaFuncAttributeMaxDynamicSharedMemorySize,
                         SMEMB2);

    seed_state<<<BHH / 256, 256>>>(h0);

    __nv_bfloat16 *xh, *xl, *wh, *wl, *uh, *ul;
    cudaGetSymbolAddress((void**)&xh, g_xh);
    cudaGetSymbolAddress((void**)&xl, g_xl);
    cudaGetSymbolAddress((void**)&wh, g_wh);
    cudaGetSymbolAddress((void**)&wl, g_wl);
    cudaGetSymbolAddress((void**)&uh, g_uh);
    cudaGetSymbolAddress((void**)&ul, g_ul);

    cvt_split<<<(SS * BB * II / 4) / 256, 256>>>(x, xh, xl);
    cvt_split<<<(G4 * II / 4) / 256, 256>>>(Ww, wh, wl);
    cvt_split<<<(G4 * HH / 4) / 256, 256>>>(Uw, uh, ul);

    gemm_xw_hmma<<<dim3(G4 / 128, (SS * BB) / 128), 256, 2 * STAGEB>>>(Wb);

    lstm_persist_v2<<<128, 256, SMEMB2>>>(c0, out);
}

// round 16
// speedup vs baseline: 1.1485x; 1.0248x over previous
#include <cuda_runtime.h>
#include <cuda_bf16.h>
#include <math.h>
#include <stdint.h>

#define SS 512
#define BB 64
#define II 1024
#define HH 1024
#define G4 4096   // 4*H
#define BHH (BB * HH)

// Scratch
__device__ float g_xw[(size_t)SS * BB * G4];       // 512 MB
__device__ float g_pex[128][64 * 32];              // pairwise partials, 1 MB
__device__ unsigned g_pflag[128];
__device__ unsigned g_stepcnt;

// bf16 hi/lo splits
__device__ __nv_bfloat16 g_xh[(size_t)SS * BB * II];   // 64 MB
__device__ __nv_bfloat16 g_xl[(size_t)SS * BB * II];
__device__ __nv_bfloat16 g_wh[(size_t)G4 * II];        // 8 MB
__device__ __nv_bfloat16 g_wl[(size_t)G4 * II];
__device__ __nv_bfloat16 g_uh[(size_t)G4 * HH];        // 8 MB
__device__ __nv_bfloat16 g_ul[(size_t)G4 * HH];
__device__ __nv_bfloat16 g_hh[2][BHH];                 // parity-buffered h
__device__ __nv_bfloat16 g_hl[2][BHH];

__device__ __forceinline__ float sigf(float x) {
    return 1.0f / (1.0f + __expf(-x));
}
__device__ __forceinline__ float tanhfast(float x) {
    return fmaf(2.0f, sigf(2.0f * x), -1.0f);
}

// ---------------- HMMA helpers (base-target ISA: sm_80+) ----------------
__device__ __forceinline__ uint32_t smem_u32(const void* p) {
    uint32_t a;
    asm("{ .reg .u64 t; cvta.to.shared.u64 t, %1; cvt.u32.u64 %0, t; }"
        : "=r"(a) : "l"(p));
    return a;
}
#define SW128(o) ((o) ^ (((o) >> 3) & 0x70))

__device__ __forceinline__ void hmma(float* c, const uint32_t* a, const uint32_t* b) {
    asm volatile(
        "mma.sync.aligned.m16n8k16.row.col.f32.bf16.bf16.f32 "
        "{%0,%1,%2,%3}, {%4,%5,%6,%7}, {%8,%9}, {%0,%1,%2,%3};"
        : "+f"(c[0]), "+f"(c[1]), "+f"(c[2]), "+f"(c[3])
        : "r"(a[0]), "r"(a[1]), "r"(a[2]), "r"(a[3]), "r"(b[0]), "r"(b[1]));
}
__device__ __forceinline__ void ldsm4(uint32_t* r, uint32_t addr) {
    asm volatile("ldmatrix.sync.aligned.m8n8.x4.shared.b16 {%0,%1,%2,%3}, [%4];"
        : "=r"(r[0]), "=r"(r[1]), "=r"(r[2]), "=r"(r[3]) : "r"(addr));
}
__device__ __forceinline__ void ldsm2(uint32_t* r, uint32_t addr) {
    asm volatile("ldmatrix.sync.aligned.m8n8.x2.shared.b16 {%0,%1}, [%2];"
        : "=r"(r[0]), "=r"(r[1]) : "r"(addr));
}
__device__ __forceinline__ void cpa16(uint32_t dst, const void* src) {
    asm volatile("cp.async.cg.shared.global [%0], [%1], 16;"
                 :: "r"(dst), "l"(src) : "memory");
}
__device__ __forceinline__ void cpa16_ca(uint32_t dst, const void* src) {
    asm volatile("cp.async.ca.shared.global [%0], [%1], 16;"
                 :: "r"(dst), "l"(src) : "memory");
}
#define CP_COMMIT() asm volatile("cp.async.commit_group;" ::: "memory")
#define CP_WAIT(n)  asm volatile("cp.async.wait_group %0;" :: "n"(n) : "memory")

// ---------------------------------------------------------------------------
// Split fp32 -> bf16 hi/lo (generic)
// ---------------------------------------------------------------------------
__device__ __forceinline__ void split4(float4 v, uint2& hi, uint2& lo) {
    __nv_bfloat16 h0 = __float2bfloat16(v.x), h1 = __float2bfloat16(v.y);
    __nv_bfloat16 h2 = __float2bfloat16(v.z), h3 = __float2bfloat16(v.w);
    __nv_bfloat16 l0 = __float2bfloat16(v.x - __bfloat162float(h0));
    __nv_bfloat16 l1 = __float2bfloat16(v.y - __bfloat162float(h1));
    __nv_bfloat16 l2 = __float2bfloat16(v.z - __bfloat162float(h2));
    __nv_bfloat16 l3 = __float2bfloat16(v.w - __bfloat162float(h3));
    __nv_bfloat162 ha(h0, h1), hb(h2, h3), la(l0, l1), lb(l2, l3);
    hi.x = *(uint32_t*)&ha; hi.y = *(uint32_t*)&hb;
    lo.x = *(uint32_t*)&la; lo.y = *(uint32_t*)&lb;
}

__global__ void cvt_split(const float* __restrict__ src,
                          __nv_bfloat16* __restrict__ dhi,
                          __nv_bfloat16* __restrict__ dlo) {
    const size_t i = (size_t)blockIdx.x * 256 + threadIdx.x;
    float4 v = *((const float4*)src + i);
    uint2 hi, lo;
    split4(v, hi, lo);
    ((uint2*)dhi)[i] = hi;
    ((uint2*)dlo)[i] = lo;
}

// ---------------------------------------------------------------------------
// Kernel A (HMMA): g_xw[m,g] = sum_i X[m,i]*W[g,i] + bias[g]  (R11 winner)
// ---------------------------------------------------------------------------
#define TCK 64
#define TERM 16384
#define STAGEB 65536
#define NSTG (II / TCK)

__global__ __launch_bounds__(256) void gemm_xw_hmma(const float* __restrict__ bias) {
    extern __shared__ __align__(1024) char dsm[];
    __shared__ float s_bias[128];

    const int tid = threadIdx.x;
    const int wid = tid >> 5;
    const int lid = tid & 31;
    const int wm = wid >> 2;
    const int wn = wid & 3;
    const int n0 = blockIdx.x << 7;
    const int m0 = blockIdx.y << 7;

    const uint32_t smbase = smem_u32(dsm);

    if (tid < 128) s_bias[tid] = bias[n0 + tid];

    const __nv_bfloat16* xh = g_xh + (size_t)m0 * II;
    const __nv_bfloat16* xl = g_xl + (size_t)m0 * II;
    const __nv_bfloat16* wh = g_wh + (size_t)n0 * II;
    const __nv_bfloat16* wl = g_wl + (size_t)n0 * II;

    uint32_t s_off[4];
    size_t g_off[4];
    #pragma unroll
    for (int j = 0; j < 4; j++) {
        const int idx = tid + (j << 8);
        const int r = idx >> 3;
        const int c = idx & 7;
        s_off[j] = SW128((uint32_t)(r * 128 + c * 16));
        g_off[j] = (size_t)r * II + c * 8;
    }

    uint32_t aRowRaw[4], bRowRaw[4];
    #pragma unroll
    for (int mi = 0; mi < 4; mi++)
        aRowRaw[mi] = (uint32_t)(((wm << 6) + (mi << 4) + (lid & 15)) * 128);
    #pragma unroll
    for (int ni = 0; ni < 4; ni++)
        bRowRaw[ni] = (uint32_t)(((wn << 5) + (ni << 3) + (lid & 7)) * 128);
    const uint32_t aChunk = (lid >> 4) << 4;
    const uint32_t bChunk = ((lid >> 3) & 1) << 4;

    float acc[4][4][4];
    #pragma unroll
    for (int mi = 0; mi < 4; mi++)
        #pragma unroll
        for (int ni = 0; ni < 4; ni++)
            #pragma unroll
            for (int q = 0; q < 4; q++) acc[mi][ni][q] = 0.0f;

    {
        const uint32_t sb = smbase;
        #pragma unroll
        for (int j = 0; j < 4; j++) {
            cpa16(sb + s_off[j],            xh + g_off[j]);
            cpa16(sb + TERM + s_off[j],     xl + g_off[j]);
            cpa16(sb + 2 * TERM + s_off[j], wh + g_off[j]);
            cpa16(sb + 3 * TERM + s_off[j], wl + g_off[j]);
        }
        CP_COMMIT();
    }

    for (int s = 0; s < NSTG; s++) {
        if (s + 1 < NSTG) {
            const uint32_t sb = smbase + ((s + 1) & 1) * STAGEB;
            const int k0 = (s + 1) * TCK;
            #pragma unroll
            for (int j = 0; j < 4; j++) {
                cpa16(sb + s_off[j],            xh + g_off[j] + k0);
                cpa16(sb + TERM + s_off[j],     xl + g_off[j] + k0);
                cpa16(sb + 2 * TERM + s_off[j], wh + g_off[j] + k0);
                cpa16(sb + 3 * TERM + s_off[j], wl + g_off[j] + k0);
            }
            CP_COMMIT();
            CP_WAIT(1);
        } else {
            CP_WAIT(0);
        }
        __syncthreads();

        const uint32_t sb = smbase + (s & 1) * STAGEB;
        #pragma unroll
        for (int kc = 0; kc < 4; kc++) {
            uint32_t ah[4][4], al[4][4], bh[4][2], bl[4][2];
            #pragma unroll
            for (int mi = 0; mi < 4; mi++) {
                const uint32_t ao = SW128(aRowRaw[mi] + (kc << 5) + aChunk);
                ldsm4(ah[mi], sb + ao);
                ldsm4(al[mi], sb + TERM + ao);
            }
            #pragma unroll
            for (int ni = 0; ni < 4; ni++) {
                const uint32_t bo = SW128(bRowRaw[ni] + (kc << 5) + bChunk);
                ldsm2(bh[ni], sb + 2 * TERM + bo);
                ldsm2(bl[ni], sb + 3 * TERM + bo);
            }
            #pragma unroll
            for (int mi = 0; mi < 4; mi++)
                #pragma unroll
                for (int ni = 0; ni < 4; ni++) {
                    hmma(acc[mi][ni], ah[mi], bh[ni]);
                    hmma(acc[mi][ni], ah[mi], bl[ni]);
                    hmma(acc[mi][ni], al[mi], bh[ni]);
                }
        }
        __syncthreads();
    }

    #pragma unroll
    for (int mi = 0; mi < 4; mi++) {
        const int mA = m0 + (wm << 6) + (mi << 4) + (lid >> 2);
        #pragma unroll
        for (int ni = 0; ni < 4; ni++) {
            const int colB = (wn << 5) + (ni << 3) + ((lid & 3) << 1);
            const float b0 = s_bias[colB], b1 = s_bias[colB + 1];
            float2 o0 = {acc[mi][ni][0] + b0, acc[mi][ni][1] + b1};
            float2 o1 = {acc[mi][ni][2] + b0, acc[mi][ni][3] + b1};
            *(float2*)(g_xw + (size_t)mA * G4 + n0 + colB)       = o0;
            *(float2*)(g_xw + (size_t)(mA + 8) * G4 + n0 + colB) = o1;
        }
    }
}

// ---------------------------------------------------------------------------
// Kernel B: PERSISTENT LSTM v3 — 2-way K split, pairwise partial exchange.
//   128 blocks = 64 nb (16 h-cols each) x 2 kb (k halves of 512).
//   B = U slice [64 gate-cols x 512 k] hi/lo SMEM-resident (128 KB).
//   A = h [64 x 512] hi/lo streamed per step (128 KB) via 3-slot ring of
//   32 KB chunks (k=128). Warp (wm=wid>>1: 16 m-rows, wn=wid&1: 32 n-cols)
//   -> acc 16m x 32n over the k half. Gates land in SMEM; the sibling
//   half (8 h-cols * 4 gates) is exchanged through g_pex + pairwise flag.
//   One global h-ready sync per step; c in registers; h parity-buffered.
// ---------------------------------------------------------------------------
#define ABUFB 32768            // ring slot: HI 16KB + LO 16KB
#define A_LO_OFF 16384
#define SM_B_HI 98304          // 3*ABUFB
#define SM_B_LO 163840
#define SMEMB2 229376
#define A_ATOM2 8192           // 64 rows * 128B
#define B_ATOM3 8192           // 64 rows * 128B

__global__ __launch_bounds__(256) void lstm_persist_v3(const float* __restrict__ c0,
                                                       float* __restrict__ out) {
    extern __shared__ __align__(1024) char dsm[];

    const int bid = blockIdx.x;           // 0..127
    const int nb = bid >> 1;              // 0..63
    const int kb = bid & 1;
    const int sib = bid ^ 1;
    const int kbase = kb << 9;            // 0 or 512
    const int tid = threadIdx.x;
    const int wid = tid >> 5;
    const int lid = tid & 31;
    const int wm = wid >> 1;              // 0..3: 16 m-rows
    const int wn = wid & 1;               // 0..1: 32 n-cols

    const uint32_t smbase = smem_u32(dsm);

    // ---- B (U slice, 64 local gate-cols x 512 k, hi+lo) load ONCE ----
    #pragma unroll
    for (int j = 0; j < 16; j++) {
        const int idx = tid + (j << 8);       // 0..4095
        const int a = idx >> 9;               // k-atom 0..7 (64k each)
        const int w = idx & 511;
        const int r = w >> 3;                 // local n row 0..63
        const int cc = w & 7;
        const int Grow = ((r >> 4) << 10) + (nb << 4) + (r & 15);
        const uint32_t so = (uint32_t)(a * B_ATOM3) +
                            SW128((uint32_t)(r * 128 + cc * 16));
        const size_t go = (size_t)Grow * HH + kbase + a * 64 + cc * 8;
        cpa16_ca(smbase + SM_B_HI + so, g_uh + go);
        cpa16_ca(smbase + SM_B_LO + so, g_ul + go);
    }
    CP_COMMIT();

    // ---- A per-chunk loader precompute (chunk = 128 k = 2 atoms) ----
    uint32_t aso[4];
    int agoR[4], agoK[4];
    #pragma unroll
    for (int j = 0; j < 4; j++) {
        const int idx = tid + (j << 8);       // 0..1023
        const int a2 = idx >> 9;              // 0..1
        const int w = idx & 511;
        const int r = w >> 3;                 // batch row 0..63
        const int cc = w & 7;
        aso[j] = (uint32_t)(a2 * A_ATOM2) +
                 SW128((uint32_t)(r * 128 + cc * 16));
        agoR[j] = r;
        agoK[j] = a2 * 64 + cc * 8;
    }

    // ---- ldmatrix bases ----
    const uint32_t aRow = (uint32_t)(((wm << 4) + (lid & 15)) * 128);
    const uint32_t aChunk = (lid >> 4) << 4;
    uint32_t bRowRaw[4];
    #pragma unroll
    for (int ni = 0; ni < 4; ni++)
        bRowRaw[ni] = (uint32_t)(((wn << 5) + (ni << 3) + (lid & 7)) * 128);
    const uint32_t bChunk = ((lid >> 3) & 1) << 4;

    // ---- combine coords: this block produces h-cols [nb*16+kb*8, +8) ----
    const int cb = tid >> 2;                  // batch 0..63
    const int jj = (tid & 3) << 1;            // 0,2,4,6
    const int hcol = (nb << 4) + (kb << 3) + jj;
    const int idxo = cb * HH + hcol;

    float2 creg = *(const float2*)(c0 + idxo);

    CP_WAIT(0);
    __syncthreads();

    volatile unsigned* sc = &g_stepcnt;
    volatile unsigned* pf = &g_pflag[sib];
    float* gs = (float*)dsm;                  // gates [64][66] fp32 (slots 0-1)
    const int sibOff = kb ? 0 : 8;            // sibling's j-range within 16

    for (int t = 0; t < SS; t++) {
        const int ph = t & 1;

        // xW prefetch (gate col = g*1024 + hcol)
        float2 gate[4];
        #pragma unroll
        for (int g = 0; g < 4; g++)
            gate[g] = *(const float2*)(g_xw + ((size_t)t * BB + cb) * G4 +
                                       (g << 10) + hcol);

        // ---- global sync: h(t) ready ----
        if (t && tid == 0) {
            const unsigned tgt = 128u * (unsigned)t;
            while (*sc < tgt) __nanosleep(32);
        }
        __syncthreads();

        const __nv_bfloat16* hhp = g_hh[ph];
        const __nv_bfloat16* hlp = g_hl[ph];

        // prologue: chunks 0 and 1
        #pragma unroll
        for (int p = 0; p < 2; p++) {
            const uint32_t ab = smbase + p * ABUFB;
            #pragma unroll
            for (int j = 0; j < 4; j++) {
                const size_t go = (size_t)agoR[j] * HH + kbase + p * 128 + agoK[j];
                cpa16(ab + aso[j], hhp + go);
                cpa16(ab + A_LO_OFF + aso[j], hlp + go);
            }
            CP_COMMIT();
        }

        float acc[4][4];
        #pragma unroll
        for (int ni = 0; ni < 4; ni++)
            #pragma unroll
            for (int q = 0; q < 4; q++) acc[ni][q] = 0.0f;

        #pragma unroll
        for (int ch = 0; ch < 4; ch++) {
            if (ch < 3) { CP_WAIT(1); } else { CP_WAIT(0); }
            __syncthreads();

            if (ch + 2 < 4) {
                const uint32_t ab = smbase + ((ch + 2) % 3) * ABUFB;
                #pragma unroll
                for (int j = 0; j < 4; j++) {
                    const size_t go = (size_t)agoR[j] * HH + kbase +
                                      (ch + 2) * 128 + agoK[j];
                    cpa16(ab + aso[j], hhp + go);
                    cpa16(ab + A_LO_OFF + aso[j], hlp + go);
                }
                CP_COMMIT();
            }

            const uint32_t ab = smbase + (ch % 3) * ABUFB;
            #pragma unroll
            for (int kk = 0; kk < 8; kk++) {
                const uint32_t aAt = (uint32_t)((kk >> 2) * A_ATOM2);
                const uint32_t kco = (uint32_t)((kk & 3) << 5);
                const uint32_t bAt = (uint32_t)((ch * 2 + (kk >> 2)) * B_ATOM3);

                uint32_t ah4[4], al4[4], bh2[4][2], bl2[4][2];
                const uint32_t ao = aAt + SW128(aRow + kco + aChunk);
                ldsm4(ah4, ab + ao);
                ldsm4(al4, ab + A_LO_OFF + ao);
                #pragma unroll
                for (int ni = 0; ni < 4; ni++) {
                    const uint32_t bo = bAt + SW128(bRowRaw[ni] + kco + bChunk);
                    ldsm2(bh2[ni], smbase + SM_B_HI + bo);
                    ldsm2(bl2[ni], smbase + SM_B_LO + bo);
                }
                #pragma unroll
                for (int ni = 0; ni < 4; ni++) {
                    hmma(acc[ni], ah4, bh2[ni]);
                    hmma(acc[ni], ah4, bl2[ni]);
                    hmma(acc[ni], al4, bh2[ni]);
                }
            }
        }
        __syncthreads();   // all warps done with ring before gates overwrite

        // ---- gates to SMEM: [64][66] fp32 ----
        #pragma unroll
        for (int ni = 0; ni < 4; ni++) {
            const int col = (wn << 5) + (ni << 3) + ((lid & 3) << 1);
            const int row = (wm << 4) + (lid >> 2);
            *(float2*)&gs[row * 66 + col] = make_float2(acc[ni][0], acc[ni][1]);
            *(float2*)&gs[(row + 8) * 66 + col] = make_float2(acc[ni][2], acc[ni][3]);
        }
        __syncthreads();

        // ---- ship sibling's half (8 h-cols x 4 gates x 64 b = 8 KB) ----
        {
            const int rr = tid >> 2;
            const int cb8 = (tid & 3) << 3;         // 0,8,16,24
            float* pex = g_pex[bid];
            #pragma unroll
            for (int q = 0; q < 4; q++) {
                const int c = cb8 + (q << 1);       // pex col (pair)
                const int g = c >> 3, jsub = c & 7;
                float2 v = make_float2(gs[rr * 66 + (g << 4) + sibOff + jsub],
                                       gs[rr * 66 + (g << 4) + sibOff + jsub + 1]);
                *(float2*)&pex[rr * 32 + c] = v;
            }
        }
        __threadfence();
        __syncthreads();
        if (tid == 0) {
            atomicAdd(&g_pflag[bid], 1u);
            while (*pf < (unsigned)(t + 1)) __nanosleep(32);
        }
        __syncthreads();

        // ---- combine + elementwise ----
        {
            #pragma unroll
            for (int g = 0; g < 4; g++) {
                // own half from smem
                gate[g].x += gs[cb * 66 + (g << 4) + (kb << 3) + jj];
                gate[g].y += gs[cb * 66 + (g << 4) + (kb << 3) + jj + 1];
                // sibling half via L2
                const float2 pv = __ldcg((const float2*)(g_pex[sib] +
                                          cb * 32 + (g << 3) + jj));
                gate[g].x += pv.x; gate[g].y += pv.y;
            }

            float2 cn, hv;
            {
                const float iv = sigf(gate[0].x), fv = sigf(gate[1].x);
                const float gv = tanhfast(gate[2].x), ov = sigf(gate[3].x);
                cn.x = fv * creg.x + iv * gv;  hv.x = ov * tanhfast(cn.x);
            }
            {
                const float iv = sigf(gate[0].y), fv = sigf(gate[1].y);
                const float gv = tanhfast(gate[2].y), ov = sigf(gate[3].y);
                cn.y = fv * creg.y + iv * gv;  hv.y = ov * tanhfast(cn.y);
            }
            creg = cn;
            *(float2*)(out + (size_t)t * BHH + idxo) = hv;

            __nv_bfloat16 h0b = __float2bfloat16(hv.x);
            __nv_bfloat16 h1b = __float2bfloat16(hv.y);
            __nv_bfloat16 l0b = __float2bfloat16(hv.x - __bfloat162float(h0b));
            __nv_bfloat16 l1b = __float2bfloat16(hv.y - __bfloat162float(h1b));
            __nv_bfloat162 hp(h0b, h1b), lp(l0b, l1b);
            *(__nv_bfloat162*)(g_hh[ph ^ 1] + idxo) = hp;
            *(__nv_bfloat162*)(g_hl[ph ^ 1] + idxo) = lp;

            if (t == SS - 1) {
                const size_t base = (size_t)SS * BHH;
                *(float2*)(out + base + idxo) = hv;          // h_t
                *(float2*)(out + base + BHH + idxo) = cn;    // c_t
            }
        }

        // ---- publish ----
        __threadfence();
        __syncthreads();
        if (tid == 0) atomicAdd(&g_stepcnt, 1u);
    }
}

// ---------------------------------------------------------------------------
// Helpers
// ---------------------------------------------------------------------------
__global__ void seed_state(const float* __restrict__ h0) {
    const int i = blockIdx.x * 256 + threadIdx.x;
    const float h = h0[i];
    const __nv_bfloat16 hh = __float2bfloat16(h);
    g_hh[0][i] = hh;
    g_hl[0][i] = __float2bfloat16(h - __bfloat162float(hh));
    if (blockIdx.x == 0) {
        if (threadIdx.x < 128) g_pflag[threadIdx.x] = 0u;
        if (threadIdx.x == 128) g_stepcnt = 0u;
    }
}

// ---------------------------------------------------------------------------
extern "C" void kernel_launch(void* const* d_in, const int* in_sizes, int n_in,
                              void* d_out, int out_size) {
    (void)in_sizes; (void)n_in; (void)out_size;
    const float* x  = (const float*)d_in[0];
    const float* h0 = (const float*)d_in[1];
    const float* c0 = (const float*)d_in[2];
    const float* Ww = (const float*)d_in[3];
    const float* Wb = (const float*)d_in[4];
    const float* Uw = (const float*)d_in[5];
    float* out = (float*)d_out;

    cudaFuncSetAttribute(gemm_xw_hmma,
                         cudaFuncAttributeMaxDynamicSharedMemorySize,
                         2 * STAGEB);
    cudaFuncSetAttribute(lstm_persist_v3,
                         cudaFuncAttributeMaxDynamicSharedMemorySize,
                         SMEMB2);

    seed_state<<<BHH / 256, 256>>>(h0);

    __nv_bfloat16 *xh, *xl, *wh, *wl, *uh, *ul;
    cudaGetSymbolAddress((void**)&xh, g_xh);
    cudaGetSymbolAddress((void**)&xl, g_xl);
    cudaGetSymbolAddress((void**)&wh, g_wh);
    cudaGetSymbolAddress((void**)&wl, g_wl);
    cudaGetSymbolAddress((void**)&uh, g_uh);
    cudaGetSymbolAddress((void**)&ul, g_ul);

    cvt_split<<<(SS * BB * II / 4) / 256, 256>>>(x, xh, xl);
    cvt_split<<<(G4 * II / 4) / 256, 256>>>(Ww, wh, wl);
    cvt_split<<<(G4 * HH / 4) / 256, 256>>>(Uw, uh, ul);

    gemm_xw_hmma<<<dim3(G4 / 128, (SS * BB) / 128), 256, 2 * STAGEB>>>(Wb);

    lstm_persist_v3<<<128, 256, SMEMB2>>>(c0, out);
}

// round 17
// speedup vs baseline: 1.1910x; 1.0371x over previous
#include <cuda_runtime.h>
#include <cuda_bf16.h>
#include <math.h>
#include <stdint.h>

#define SS 512
#define BB 64
#define II 1024
#define HH 1024
#define G4 4096   // 4*H
#define BHH (BB * HH)

// Scratch
__device__ float g_xw[(size_t)SS * BB * G4];       // 512 MB
__device__ unsigned g_stepcnt;

// bf16 hi/lo splits
__device__ __nv_bfloat16 g_xh[(size_t)SS * BB * II];   // 64 MB
__device__ __nv_bfloat16 g_xl[(size_t)SS * BB * II];
__device__ __nv_bfloat16 g_wh[(size_t)G4 * II];        // 8 MB
__device__ __nv_bfloat16 g_wl[(size_t)G4 * II];
__device__ __nv_bfloat16 g_uh[(size_t)G4 * HH];        // 8 MB
__device__ __nv_bfloat16 g_ul[(size_t)G4 * HH];
__device__ __nv_bfloat16 g_hh[2][BHH];                 // parity-buffered h
__device__ __nv_bfloat16 g_hl[2][BHH];

__device__ __forceinline__ float sigf(float x) {
    return 1.0f / (1.0f + __expf(-x));
}
__device__ __forceinline__ float tanhfast(float x) {
    return fmaf(2.0f, sigf(2.0f * x), -1.0f);
}

// ---------------- HMMA helpers (base-target ISA: sm_80+/sm_90) ----------------
__device__ __forceinline__ uint32_t smem_u32(const void* p) {
    uint32_t a;
    asm("{ .reg .u64 t; cvta.to.shared.u64 t, %1; cvt.u32.u64 %0, t; }"
        : "=r"(a) : "l"(p));
    return a;
}
#define SW128(o) ((o) ^ (((o) >> 3) & 0x70))

__device__ __forceinline__ void hmma(float* c, const uint32_t* a, const uint32_t* b) {
    asm volatile(
        "mma.sync.aligned.m16n8k16.row.col.f32.bf16.bf16.f32 "
        "{%0,%1,%2,%3}, {%4,%5,%6,%7}, {%8,%9}, {%0,%1,%2,%3};"
        : "+f"(c[0]), "+f"(c[1]), "+f"(c[2]), "+f"(c[3])
        : "r"(a[0]), "r"(a[1]), "r"(a[2]), "r"(a[3]), "r"(b[0]), "r"(b[1]));
}
__device__ __forceinline__ void ldsm4(uint32_t* r, uint32_t addr) {
    asm volatile("ldmatrix.sync.aligned.m8n8.x4.shared.b16 {%0,%1,%2,%3}, [%4];"
        : "=r"(r[0]), "=r"(r[1]), "=r"(r[2]), "=r"(r[3]) : "r"(addr));
}
__device__ __forceinline__ void ldsm2(uint32_t* r, uint32_t addr) {
    asm volatile("ldmatrix.sync.aligned.m8n8.x2.shared.b16 {%0,%1}, [%2];"
        : "=r"(r[0]), "=r"(r[1]) : "r"(addr));
}
__device__ __forceinline__ void cpa16(uint32_t dst, const void* src) {
    asm volatile("cp.async.cg.shared.global [%0], [%1], 16;"
                 :: "r"(dst), "l"(src) : "memory");
}
__device__ __forceinline__ void cpa16_ca(uint32_t dst, const void* src) {
    asm volatile("cp.async.ca.shared.global [%0], [%1], 16;"
                 :: "r"(dst), "l"(src) : "memory");
}
#define CP_COMMIT() asm volatile("cp.async.commit_group;" ::: "memory")
#define CP_WAIT(n)  asm volatile("cp.async.wait_group %0;" :: "n"(n) : "memory")

// ---------------------------------------------------------------------------
// Split fp32 -> bf16 hi/lo (generic)
// ---------------------------------------------------------------------------
__device__ __forceinline__ void split4(float4 v, uint2& hi, uint2& lo) {
    __nv_bfloat16 h0 = __float2bfloat16(v.x), h1 = __float2bfloat16(v.y);
    __nv_bfloat16 h2 = __float2bfloat16(v.z), h3 = __float2bfloat16(v.w);
    __nv_bfloat16 l0 = __float2bfloat16(v.x - __bfloat162float(h0));
    __nv_bfloat16 l1 = __float2bfloat16(v.y - __bfloat162float(h1));
    __nv_bfloat16 l2 = __float2bfloat16(v.z - __bfloat162float(h2));
    __nv_bfloat16 l3 = __float2bfloat16(v.w - __bfloat162float(h3));
    __nv_bfloat162 ha(h0, h1), hb(h2, h3), la(l0, l1), lb(l2, l3);
    hi.x = *(uint32_t*)&ha; hi.y = *(uint32_t*)&hb;
    lo.x = *(uint32_t*)&la; lo.y = *(uint32_t*)&lb;
}

__global__ void cvt_split(const float* __restrict__ src,
                          __nv_bfloat16* __restrict__ dhi,
                          __nv_bfloat16* __restrict__ dlo) {
    const size_t i = (size_t)blockIdx.x * 256 + threadIdx.x;
    float4 v = *((const float4*)src + i);
    uint2 hi, lo;
    split4(v, hi, lo);
    ((uint2*)dhi)[i] = hi;
    ((uint2*)dlo)[i] = lo;
}

// ---------------------------------------------------------------------------
// Kernel A (HMMA): g_xw[m,g] = sum_i X[m,i]*W[g,i] + bias[g]  (R11 winner)
// ---------------------------------------------------------------------------
#define TCK 64
#define TERM 16384
#define STAGEB 65536
#define NSTG (II / TCK)

__global__ __launch_bounds__(256) void gemm_xw_hmma(const float* __restrict__ bias) {
    extern __shared__ __align__(1024) char dsm[];
    __shared__ float s_bias[128];

    const int tid = threadIdx.x;
    const int wid = tid >> 5;
    const int lid = tid & 31;
    const int wm = wid >> 2;
    const int wn = wid & 3;
    const int n0 = blockIdx.x << 7;
    const int m0 = blockIdx.y << 7;

    const uint32_t smbase = smem_u32(dsm);

    if (tid < 128) s_bias[tid] = bias[n0 + tid];

    const __nv_bfloat16* xh = g_xh + (size_t)m0 * II;
    const __nv_bfloat16* xl = g_xl + (size_t)m0 * II;
    const __nv_bfloat16* wh = g_wh + (size_t)n0 * II;
    const __nv_bfloat16* wl = g_wl + (size_t)n0 * II;

    uint32_t s_off[4];
    size_t g_off[4];
    #pragma unroll
    for (int j = 0; j < 4; j++) {
        const int idx = tid + (j << 8);
        const int r = idx >> 3;
        const int c = idx & 7;
        s_off[j] = SW128((uint32_t)(r * 128 + c * 16));
        g_off[j] = (size_t)r * II + c * 8;
    }

    uint32_t aRowRaw[4], bRowRaw[4];
    #pragma unroll
    for (int mi = 0; mi < 4; mi++)
        aRowRaw[mi] = (uint32_t)(((wm << 6) + (mi << 4) + (lid & 15)) * 128);
    #pragma unroll
    for (int ni = 0; ni < 4; ni++)
        bRowRaw[ni] = (uint32_t)(((wn << 5) + (ni << 3) + (lid & 7)) * 128);
    const uint32_t aChunk = (lid >> 4) << 4;
    const uint32_t bChunk = ((lid >> 3) & 1) << 4;

    float acc[4][4][4];
    #pragma unroll
    for (int mi = 0; mi < 4; mi++)
        #pragma unroll
        for (int ni = 0; ni < 4; ni++)
            #pragma unroll
            for (int q = 0; q < 4; q++) acc[mi][ni][q] = 0.0f;

    {
        const uint32_t sb = smbase;
        #pragma unroll
        for (int j = 0; j < 4; j++) {
            cpa16(sb + s_off[j],            xh + g_off[j]);
            cpa16(sb + TERM + s_off[j],     xl + g_off[j]);
            cpa16(sb + 2 * TERM + s_off[j], wh + g_off[j]);
            cpa16(sb + 3 * TERM + s_off[j], wl + g_off[j]);
        }
        CP_COMMIT();
    }

    for (int s = 0; s < NSTG; s++) {
        if (s + 1 < NSTG) {
            const uint32_t sb = smbase + ((s + 1) & 1) * STAGEB;
            const int k0 = (s + 1) * TCK;
            #pragma unroll
            for (int j = 0; j < 4; j++) {
                cpa16(sb + s_off[j],            xh + g_off[j] + k0);
                cpa16(sb + TERM + s_off[j],     xl + g_off[j] + k0);
                cpa16(sb + 2 * TERM + s_off[j], wh + g_off[j] + k0);
                cpa16(sb + 3 * TERM + s_off[j], wl + g_off[j] + k0);
            }
            CP_COMMIT();
            CP_WAIT(1);
        } else {
            CP_WAIT(0);
        }
        __syncthreads();

        const uint32_t sb = smbase + (s & 1) * STAGEB;
        #pragma unroll
        for (int kc = 0; kc < 4; kc++) {
            uint32_t ah[4][4], al[4][4], bh[4][2], bl[4][2];
            #pragma unroll
            for (int mi = 0; mi < 4; mi++) {
                const uint32_t ao = SW128(aRowRaw[mi] + (kc << 5) + aChunk);
                ldsm4(ah[mi], sb + ao);
                ldsm4(al[mi], sb + TERM + ao);
            }
            #pragma unroll
            for (int ni = 0; ni < 4; ni++) {
                const uint32_t bo = SW128(bRowRaw[ni] + (kc << 5) + bChunk);
                ldsm2(bh[ni], sb + 2 * TERM + bo);
                ldsm2(bl[ni], sb + 3 * TERM + bo);
            }
            #pragma unroll
            for (int mi = 0; mi < 4; mi++)
                #pragma unroll
                for (int ni = 0; ni < 4; ni++) {
                    hmma(acc[mi][ni], ah[mi], bh[ni]);
                    hmma(acc[mi][ni], ah[mi], bl[ni]);
                    hmma(acc[mi][ni], al[mi], bh[ni]);
                }
        }
        __syncthreads();
    }

    #pragma unroll
    for (int mi = 0; mi < 4; mi++) {
        const int mA = m0 + (wm << 6) + (mi << 4) + (lid >> 2);
        #pragma unroll
        for (int ni = 0; ni < 4; ni++) {
            const int colB = (wn << 5) + (ni << 3) + ((lid & 3) << 1);
            const float b0 = s_bias[colB], b1 = s_bias[colB + 1];
            float2 o0 = {acc[mi][ni][0] + b0, acc[mi][ni][1] + b1};
            float2 o1 = {acc[mi][ni][2] + b0, acc[mi][ni][3] + b1};
            *(float2*)(g_xw + (size_t)mA * G4 + n0 + colB)       = o0;
            *(float2*)(g_xw + (size_t)(mA + 8) * G4 + n0 + colB) = o1;
        }
    }
}

// ---------------------------------------------------------------------------
// Kernel B: PERSISTENT LSTM v4 — 2-way K split, DSMEM pairwise exchange.
//   Cluster (2,1,1): pair = (nb, kb=0/1). 128 blocks = 64 clusters.
//   B = U slice [64 gate-cols x 512 k] hi/lo SMEM-resident (128 KB).
//   A = h [64 x 512] hi/lo per step via depth-2 ring of 32 KB chunks.
//   B-side fragments loaded with ldmatrix.x4 (16 cols x 16 k per instr).
//   Gate sibling-half shipped straight into sibling SMEM (mapa +
//   st.shared::cluster), ordered by one cluster barrier. Cross-step WAR on
//   pex is protected by the global h-ready counter.
//   SMEM map: ring 0..64K | pex_in 64K..72K | gates 72K.. | B_HI 96K | B_LO 160K
// ---------------------------------------------------------------------------
#define ABUFB 32768            // ring slot: HI 16KB + LO 16KB
#define A_LO_OFF 16384
#define PEX_OFF 65536          // 8 KB sibling partials (written by sibling)
#define GS_OFF  73728          // gates [64][66] fp32 = 16896 B
#define SM_B_HI 98304
#define SM_B_LO 163840
#define SMEMB2 229376
#define A_ATOM2 8192           // 64 rows * 128B
#define B_ATOM3 8192           // 64 rows * 128B

__global__ __launch_bounds__(256) __cluster_dims__(2, 1, 1)
void lstm_persist_v4(const float* __restrict__ c0, float* __restrict__ out) {
    extern __shared__ __align__(1024) char dsm[];

    const int bid = blockIdx.x;           // 0..127
    const int nb = bid >> 1;              // 0..63
    const int kb = bid & 1;
    const int kbase = kb << 9;            // 0 or 512
    const int tid = threadIdx.x;
    const int wid = tid >> 5;
    const int lid = tid & 31;
    const int wm = wid >> 1;              // 0..3: 16 m-rows
    const int wn = wid & 1;               // 0..1: 32 n-cols

    uint32_t myrank;
    asm("mov.u32 %0, %%cluster_ctarank;" : "=r"(myrank));
    const uint32_t sibrank = myrank ^ 1u;

    const uint32_t smbase = smem_u32(dsm);

    // ---- B (U slice, 64 local gate-cols x 512 k, hi+lo) load ONCE ----
    #pragma unroll
    for (int j = 0; j < 16; j++) {
        const int idx = tid + (j << 8);       // 0..4095
        const int a = idx >> 9;               // k-atom 0..7 (64k each)
        const int w = idx & 511;
        const int r = w >> 3;                 // local n row 0..63
        const int cc = w & 7;
        const int Grow = ((r >> 4) << 10) + (nb << 4) + (r & 15);
        const uint32_t so = (uint32_t)(a * B_ATOM3) +
                            SW128((uint32_t)(r * 128 + cc * 16));
        const size_t go = (size_t)Grow * HH + kbase + a * 64 + cc * 8;
        cpa16_ca(smbase + SM_B_HI + so, g_uh + go);
        cpa16_ca(smbase + SM_B_LO + so, g_ul + go);
    }
    CP_COMMIT();

    // ---- A per-chunk loader precompute (chunk = 128 k = 2 atoms) ----
    uint32_t aso[4];
    int agoR[4], agoK[4];
    #pragma unroll
    for (int j = 0; j < 4; j++) {
        const int idx = tid + (j << 8);       // 0..1023
        const int a2 = idx >> 9;              // 0..1
        const int w = idx & 511;
        const int r = w >> 3;                 // batch row 0..63
        const int cc = w & 7;
        aso[j] = (uint32_t)(a2 * A_ATOM2) +
                 SW128((uint32_t)(r * 128 + cc * 16));
        agoR[j] = r;
        agoK[j] = a2 * 64 + cc * 8;
    }

    // ---- ldmatrix bases ----
    const uint32_t aRow = (uint32_t)(((wm << 4) + (lid & 15)) * 128);
    const uint32_t aChunk = (lid >> 4) << 4;
    // B x4: lane row = wn*32 + ni2*16 + ((lid>>4)&1)*8 + (lid&7),
    //       chunk = ((lid>>3)&1)*16. Frags: {b0(ni),b1(ni),b0(ni+8),b1(ni+8)}
    uint32_t bRow2[2];
    #pragma unroll
    for (int n2 = 0; n2 < 2; n2++)
        bRow2[n2] = (uint32_t)(((wn << 5) + (n2 << 4) +
                                (((lid >> 4) & 1) << 3) + (lid & 7)) * 128);
    const uint32_t bChunk = ((lid >> 3) & 1) << 4;

    // ---- combine coords: this block produces h-cols [nb*16+kb*8, +8) ----
    const int cb = tid >> 2;                  // batch 0..63
    const int jj = (tid & 3) << 1;            // 0,2,4,6
    const int hcol = (nb << 4) + (kb << 3) + jj;
    const int idxo = cb * HH + hcol;

    float2 creg = *(const float2*)(c0 + idxo);

    CP_WAIT(0);
    __syncthreads();

    volatile unsigned* sc = &g_stepcnt;
    float* gs = (float*)(dsm + GS_OFF);       // [64][66] fp32
    float* pexIn = (float*)(dsm + PEX_OFF);   // [64][32] fp32 (from sibling)
    const int sibOff = kb ? 0 : 8;            // sibling's j-range within 16

    // Precompute DSMEM remote addresses for the 4 float2 this thread ships.
    uint32_t remAddr[4];
    {
        const int rr = tid >> 2;
        const int cb8 = (tid & 3) << 3;
        #pragma unroll
        for (int q = 0; q < 4; q++) {
            const int c = cb8 + (q << 1);
            const uint32_t loc = smbase + PEX_OFF +
                                 (uint32_t)(rr * 32 + c) * 4u;
            asm("mapa.shared::cluster.u32 %0, %1, %2;"
                : "=r"(remAddr[q]) : "r"(loc), "r"(sibrank));
        }
    }

    for (int t = 0; t < SS; t++) {
        const int ph = t & 1;

        // xW prefetch (gate col = g*1024 + hcol)
        float2 gate[4];
        #pragma unroll
        for (int g = 0; g < 4; g++)
            gate[g] = *(const float2*)(g_xw + ((size_t)t * BB + cb) * G4 +
                                       (g << 10) + hcol);

        // ---- global sync: h(t) ready ----
        if (t && tid == 0) {
            const unsigned tgt = 128u * (unsigned)t;
            while (*sc < tgt) __nanosleep(32);
        }
        __syncthreads();

        const __nv_bfloat16* hhp = g_hh[ph];
        const __nv_bfloat16* hlp = g_hl[ph];

        // prologue: chunk 0 -> slot 0
        {
            const uint32_t ab = smbase;
            #pragma unroll
            for (int j = 0; j < 4; j++) {
                const size_t go = (size_t)agoR[j] * HH + kbase + agoK[j];
                cpa16(ab + aso[j], hhp + go);
                cpa16(ab + A_LO_OFF + aso[j], hlp + go);
            }
            CP_COMMIT();
        }

        float acc[4][4];
        #pragma unroll
        for (int ni = 0; ni < 4; ni++)
            #pragma unroll
            for (int q = 0; q < 4; q++) acc[ni][q] = 0.0f;

        #pragma unroll
        for (int ch = 0; ch < 4; ch++) {
            if (ch + 1 < 4) {
                const uint32_t ab = smbase + ((ch + 1) & 1) * ABUFB;
                #pragma unroll
                for (int j = 0; j < 4; j++) {
                    const size_t go = (size_t)agoR[j] * HH + kbase +
                                      (ch + 1) * 128 + agoK[j];
                    cpa16(ab + aso[j], hhp + go);
                    cpa16(ab + A_LO_OFF + aso[j], hlp + go);
                }
                CP_COMMIT();
                CP_WAIT(1);
            } else {
                CP_WAIT(0);
            }
            __syncthreads();

            const uint32_t ab = smbase + (ch & 1) * ABUFB;
            #pragma unroll
            for (int kk = 0; kk < 8; kk++) {
                const uint32_t aAt = (uint32_t)((kk >> 2) * A_ATOM2);
                const uint32_t kco = (uint32_t)((kk & 3) << 5);
                const uint32_t bAt = (uint32_t)((ch * 2 + (kk >> 2)) * B_ATOM3);

                uint32_t ah4[4], al4[4], bh4[2][4], bl4[2][4];
                const uint32_t ao = aAt + SW128(aRow + kco + aChunk);
                ldsm4(ah4, ab + ao);
                ldsm4(al4, ab + A_LO_OFF + ao);
                #pragma unroll
                for (int n2 = 0; n2 < 2; n2++) {
                    const uint32_t bo = bAt + SW128(bRow2[n2] + kco + bChunk);
                    ldsm4(bh4[n2], smbase + SM_B_HI + bo);
                    ldsm4(bl4[n2], smbase + SM_B_LO + bo);
                }
                #pragma unroll
                for (int n2 = 0; n2 < 2; n2++) {
                    hmma(acc[n2 * 2],     ah4, &bh4[n2][0]);
                    hmma(acc[n2 * 2],     ah4, &bl4[n2][0]);
                    hmma(acc[n2 * 2],     al4, &bh4[n2][0]);
                    hmma(acc[n2 * 2 + 1], ah4, &bh4[n2][2]);
                    hmma(acc[n2 * 2 + 1], ah4, &bl4[n2][2]);
                    hmma(acc[n2 * 2 + 1], al4, &bh4[n2][2]);
                }
            }
            __syncthreads();   // slot reuse at ch+2 (issued next iteration)
        }

        // ---- gates to SMEM: [64][66] fp32 ----
        #pragma unroll
        for (int ni = 0; ni < 4; ni++) {
            const int col = (wn << 5) + (ni << 3) + ((lid & 3) << 1);
            const int row = (wm << 4) + (lid >> 2);
            *(float2*)&gs[row * 66 + col] = make_float2(acc[ni][0], acc[ni][1]);
            *(float2*)&gs[(row + 8) * 66 + col] = make_float2(acc[ni][2], acc[ni][3]);
        }
        __syncthreads();

        // ---- ship sibling's half straight into sibling SMEM (DSMEM) ----
        {
            const int rr = tid >> 2;
            const int cb8 = (tid & 3) << 3;
            #pragma unroll
            for (int q = 0; q < 4; q++) {
                const int c = cb8 + (q << 1);
                const int g = c >> 3, jsub = c & 7;
                const float vx = gs[rr * 66 + (g << 4) + sibOff + jsub];
                const float vy = gs[rr * 66 + (g << 4) + sibOff + jsub + 1];
                asm volatile("st.shared::cluster.v2.f32 [%0], {%1, %2};"
                             :: "r"(remAddr[q]), "f"(vx), "f"(vy) : "memory");
            }
        }
        asm volatile("barrier.cluster.arrive.aligned;" ::: "memory");
        asm volatile("barrier.cluster.wait.aligned;" ::: "memory");

        // ---- combine + elementwise ----
        {
            #pragma unroll
            for (int g = 0; g < 4; g++) {
                gate[g].x += gs[cb * 66 + (g << 4) + (kb << 3) + jj] +
                             pexIn[cb * 32 + (g << 3) + jj];
                gate[g].y += gs[cb * 66 + (g << 4) + (kb << 3) + jj + 1] +
                             pexIn[cb * 32 + (g << 3) + jj + 1];
            }

            float2 cn, hv;
            {
                const float iv = sigf(gate[0].x), fv = sigf(gate[1].x);
                const float gv = tanhfast(gate[2].x), ov = sigf(gate[3].x);
                cn.x = fv * creg.x + iv * gv;  hv.x = ov * tanhfast(cn.x);
            }
            {
                const float iv = sigf(gate[0].y), fv = sigf(gate[1].y);
                const float gv = tanhfast(gate[2].y), ov = sigf(gate[3].y);
                cn.y = fv * creg.y + iv * gv;  hv.y = ov * tanhfast(cn.y);
            }
            creg = cn;
            *(float2*)(out + (size_t)t * BHH + idxo) = hv;

            __nv_bfloat16 h0b = __float2bfloat16(hv.x);
            __nv_bfloat16 h1b = __float2bfloat16(hv.y);
            __nv_bfloat16 l0b = __float2bfloat16(hv.x - __bfloat162float(h0b));
            __nv_bfloat16 l1b = __float2bfloat16(hv.y - __bfloat162float(h1b));
            __nv_bfloat162 hp(h0b, h1b), lp(l0b, l1b);
            *(__nv_bfloat162*)(g_hh[ph ^ 1] + idxo) = hp;
            *(__nv_bfloat162*)(g_hl[ph ^ 1] + idxo) = lp;

            if (t == SS - 1) {
                const size_t base = (size_t)SS * BHH;
                *(float2*)(out + base + idxo) = hv;          // h_t
                *(float2*)(out + base + BHH + idxo) = cn;    // c_t
            }
        }

        // ---- publish ----
        __threadfence();
        __syncthreads();
        if (tid == 0) atomicAdd(&g_stepcnt, 1u);
    }
}

// ---------------------------------------------------------------------------
// Helpers
// ---------------------------------------------------------------------------
__global__ void seed_state(const float* __restrict__ h0) {
    const int i = blockIdx.x * 256 + threadIdx.x;
    const float h = h0[i];
    const __nv_bfloat16 hh = __float2bfloat16(h);
    g_hh[0][i] = hh;
    g_hl[0][i] = __float2bfloat16(h - __bfloat162float(hh));
    if (blockIdx.x == 0 && threadIdx.x == 0) g_stepcnt = 0u;
}

// ---------------------------------------------------------------------------
extern "C" void kernel_launch(void* const* d_in, const int* in_sizes, int n_in,
                              void* d_out, int out_size) {
    (void)in_sizes; (void)n_in; (void)out_size;
    const float* x  = (const float*)d_in[0];
    const float* h0 = (const float*)d_in[1];
    const float* c0 = (const float*)d_in[2];
    const float* Ww = (const float*)d_in[3];
    const float* Wb = (const float*)d_in[4];
    const float* Uw = (const float*)d_in[5];
    float* out = (float*)d_out;

    cudaFuncSetAttribute(gemm_xw_hmma,
                         cudaFuncAttributeMaxDynamicSharedMemorySize,
                         2 * STAGEB);
    cudaFuncSetAttribute(lstm_persist_v4,
                         cudaFuncAttributeMaxDynamicSharedMemorySize,
                         SMEMB2);

    seed_state<<<BHH / 256, 256>>>(h0);

    __nv_bfloat16 *xh, *xl, *wh, *wl, *uh, *ul;
    cudaGetSymbolAddress((void**)&xh, g_xh);
    cudaGetSymbolAddress((void**)&xl, g_xl);
    cudaGetSymbolAddress((void**)&wh, g_wh);
    cudaGetSymbolAddress((void**)&wl, g_wl);
    cudaGetSymbolAddress((void**)&uh, g_uh);
    cudaGetSymbolAddress((void**)&ul, g_ul);

    cvt_split<<<(SS * BB * II / 4) / 256, 256>>>(x, xh, xl);
    cvt_split<<<(G4 * II / 4) / 256, 256>>>(Ww, wh, wl);
    cvt_split<<<(G4 * HH / 4) / 256, 256>>>(Uw, uh, ul);

    gemm_xw_hmma<<<dim3(G4 / 128, (SS * BB) / 128), 256, 2 * STAGEB>>>(Wb);

    lstm_persist_v4<<<128, 256, SMEMB2>>>(c0, out);
}